// round 1
// baseline (speedup 1.0000x reference)
#include <cuda_runtime.h>
#include <cuda_bf16.h>
#include <math_constants.h>

#define N_USERS   100000
#define M_ITEMS   50000
#define N_NODES   (N_USERS + M_ITEMS)
#define LATENT    64
#define N_CATS    1000
#define N_LAYERS  3
#define TIME_BINS 24
#define NNZ       4800000
#define BATCH     1024
#define ALPHA     0.5f
#define M_PAD     50048          // 391 * 128

#define NODEF (N_NODES * LATENT)   // 9.6M floats

// ---------------- device scratch (static: no allocs allowed) ----------------
__device__ float g_e0[NODEF];
__device__ float g_e1[NODEF];
__device__ float g_acc[NODEF];
__device__ float g_Q[BATCH * 128];
__device__ float g_item[M_PAD * 128];

// ---------------- helpers ----------------
__device__ __forceinline__ void red_add_v4(float* addr, float4 v) {
    asm volatile("red.global.add.v4.f32 [%0], {%1,%2,%3,%4};"
                 :: "l"(addr), "f"(v.x), "f"(v.y), "f"(v.z), "f"(v.w)
                 : "memory");
}

// ---------------- init: e0 = acc = concat(user_emb, item_emb) ----------------
__global__ void k_init(const float* __restrict__ ue, const float* __restrict__ ie,
                       float* __restrict__ e0, float* __restrict__ acc) {
    int i = blockIdx.x * blockDim.x + threadIdx.x;       // float4 index
    const int total = N_NODES * (LATENT / 4);
    const int usplit = N_USERS * (LATENT / 4);
    if (i < total) {
        float4 v = (i < usplit) ? ((const float4*)ue)[i]
                                : ((const float4*)ie)[i - usplit];
        ((float4*)e0)[i] = v;
        ((float4*)acc)[i] = v;
    }
}

// ---------------- scatter: edst[row] += val * esrc[col], 16 threads / edge ----------------
__global__ void k_scatter(const float* __restrict__ vals,
                          const int*   __restrict__ rows,
                          const int*   __restrict__ cols,
                          const float* __restrict__ esrc,
                          float*       __restrict__ edst) {
    int g = blockIdx.x * blockDim.x + threadIdx.x;
    int edge = g >> 4;
    int t    = g & 15;
    if (edge < NNZ) {
        float v = __ldg(&vals[edge]);
        int   r = __ldg(&rows[edge]);
        int   c = __ldg(&cols[edge]);
        float4 m = ((const float4*)esrc)[c * (LATENT / 4) + t];
        m.x *= v; m.y *= v; m.z *= v; m.w *= v;
        red_add_v4(&edst[r * LATENT + t * 4], m);
    }
}

// ---------------- acc += e ----------------
__global__ void k_accum(float* __restrict__ acc, const float* __restrict__ e) {
    int i = blockIdx.x * blockDim.x + threadIdx.x;
    const int total = NODEF / 4;
    if (i < total) {
        float4 a = ((const float4*)acc)[i];
        float4 b = ((const float4*)e)[i];
        a.x += b.x; a.y += b.y; a.z += b.z; a.w += b.w;
        ((float4*)acc)[i] = a;
    }
}

// ---------------- clock: build Q[b] = [0.25*acc[user] | alpha * v_clock] ----------------
__global__ void k_clock(const float* __restrict__ acc,
                        const float* __restrict__ cat_emb,
                        const int*   __restrict__ uh3,
                        const int*   __restrict__ users,
                        const float* __restrict__ thetas,
                        float*       __restrict__ Q) {
    int b = blockIdx.x;
    int d = threadIdx.x;       // 64 threads
    __shared__ float w[TIME_BINS];
    __shared__ float sinv;
    int u = users[b];
    if (d < TIME_BINS) {
        float cur = thetas[b] * (float)(TIME_BINS / (2.0 * CUDART_PI));
        float diff = fabsf(cur - (float)d);
        float delta = fminf(diff, (float)TIME_BINS - diff);
        w[d] = __expf(-0.5f * delta * delta);
    }
    __syncthreads();
    if (d == 0) {
        float s = 0.f;
        #pragma unroll
        for (int h = 0; h < TIME_BINS; h++) s += w[h];
        sinv = 1.0f / (s + 1e-8f);
    }
    __syncthreads();
    float inv3 = sinv * (1.0f / 3.0f);
    float v = 0.f;
    const int* base = &uh3[u * TIME_BINS * 3];
    #pragma unroll 4
    for (int h = 0; h < TIME_BINS; h++) {
        int c0 = base[h * 3 + 0], c1 = base[h * 3 + 1], c2 = base[h * 3 + 2];
        float e = cat_emb[c0 * 64 + d] + cat_emb[c1 * 64 + d] + cat_emb[c2 * 64 + d];
        v += w[h] * e;
    }
    v *= inv3;
    Q[b * 128 + d]      = 0.25f * acc[u * LATENT + d];
    Q[b * 128 + 64 + d] = ALPHA * v;
}

// ---------------- items: IT[m] = [0.25*acc[N_USERS+m] | cat_emb[item_cat[m]]] ----------------
__global__ void k_items(const float* __restrict__ acc,
                        const float* __restrict__ cat_emb,
                        const int*   __restrict__ item_cat,
                        float*       __restrict__ IT) {
    int g = blockIdx.x * blockDim.x + threadIdx.x;
    int m = g >> 6;
    int d = g & 63;
    if (m < M_PAD) {
        if (m < M_ITEMS) {
            IT[m * 128 + d]      = 0.25f * acc[(N_USERS + m) * LATENT + d];
            IT[m * 128 + 64 + d] = cat_emb[item_cat[m] * 64 + d];
        } else {
            IT[m * 128 + d] = 0.f;
            IT[m * 128 + 64 + d] = 0.f;
        }
    }
}

// ---------------- GEMM: C[1024,50000] = Q[1024,128] @ IT[M_PAD,128]^T ----------------
#define BM 128
#define BN 128
#define BK 8
#define TM 8
#define TN 8

__global__ __launch_bounds__(256) void k_gemm(const float* __restrict__ A,
                                              const float* __restrict__ B,
                                              float* __restrict__ C) {
    __shared__ float As[BK][BM];
    __shared__ float Bs[BK][BN];
    const int tid  = threadIdx.x;
    const int row0 = blockIdx.y * BM;   // batch offset
    const int col0 = blockIdx.x * BN;   // item offset
    const int ty   = tid / 16;
    const int tx   = tid % 16;

    float acc[TM][TN];
    #pragma unroll
    for (int i = 0; i < TM; i++)
        #pragma unroll
        for (int j = 0; j < TN; j++) acc[i][j] = 0.f;

    const int lr = tid >> 1;          // 0..127
    const int lk = (tid & 1) * 4;     // 0 or 4

    #pragma unroll 1
    for (int k0 = 0; k0 < 128; k0 += BK) {
        float4 av = *(const float4*)(A + (row0 + lr) * 128 + k0 + lk);
        float4 bv = *(const float4*)(B + (col0 + lr) * 128 + k0 + lk);
        As[lk + 0][lr] = av.x; As[lk + 1][lr] = av.y;
        As[lk + 2][lr] = av.z; As[lk + 3][lr] = av.w;
        Bs[lk + 0][lr] = bv.x; Bs[lk + 1][lr] = bv.y;
        Bs[lk + 2][lr] = bv.z; Bs[lk + 3][lr] = bv.w;
        __syncthreads();
        #pragma unroll
        for (int kk = 0; kk < BK; kk++) {
            float a[TM], b[TN];
            #pragma unroll
            for (int i = 0; i < TM; i++) a[i] = As[kk][ty * TM + i];
            #pragma unroll
            for (int j = 0; j < TN; j++) b[j] = Bs[kk][tx * TN + j];
            #pragma unroll
            for (int i = 0; i < TM; i++)
                #pragma unroll
                for (int j = 0; j < TN; j++)
                    acc[i][j] += a[i] * b[j];
        }
        __syncthreads();
    }

    // store (vectorized; 50000 % 4 == 0 so float4 never straddles the edge)
    #pragma unroll
    for (int i = 0; i < TM; i++) {
        int r = row0 + ty * TM + i;            // always < 1024
        #pragma unroll
        for (int j = 0; j < TN; j += 4) {
            int c = col0 + tx * TN + j;
            if (c < M_ITEMS) {
                float4 v = make_float4(acc[i][j], acc[i][j + 1], acc[i][j + 2], acc[i][j + 3]);
                *(float4*)(C + r * M_ITEMS + c) = v;
            }
        }
    }
}

// ---------------- launch ----------------
extern "C" void kernel_launch(void* const* d_in, const int* in_sizes, int n_in,
                              void* d_out, int out_size) {
    const float* user_emb  = (const float*)d_in[0];
    const float* item_emb  = (const float*)d_in[1];
    const float* cat_emb   = (const float*)d_in[2];
    const float* graph_vals= (const float*)d_in[3];
    const int*   graph_rows= (const int*)  d_in[4];
    const int*   graph_cols= (const int*)  d_in[5];
    const int*   uh3       = (const int*)  d_in[6];
    const int*   item_cat  = (const int*)  d_in[7];
    const int*   users     = (const int*)  d_in[8];
    const float* thetas    = (const float*)d_in[9];
    float* out = (float*)d_out;

    float *d_e0, *d_e1, *d_acc, *d_Q, *d_item;
    cudaGetSymbolAddress((void**)&d_e0,   g_e0);
    cudaGetSymbolAddress((void**)&d_e1,   g_e1);
    cudaGetSymbolAddress((void**)&d_acc,  g_acc);
    cudaGetSymbolAddress((void**)&d_Q,    g_Q);
    cudaGetSymbolAddress((void**)&d_item, g_item);

    // init
    {
        int total = N_NODES * (LATENT / 4);
        k_init<<<(total + 255) / 256, 256>>>(user_emb, item_emb, d_e0, d_acc);
    }

    // 3 LightGCN layers
    float* e_src = d_e0;
    float* e_dst = d_e1;
    for (int l = 0; l < N_LAYERS; l++) {
        cudaMemsetAsync(e_dst, 0, (size_t)NODEF * sizeof(float), 0);
        {
            long long th = (long long)NNZ * 16;
            int blocks = (int)((th + 255) / 256);
            k_scatter<<<blocks, 256>>>(graph_vals, graph_rows, graph_cols, e_src, e_dst);
        }
        {
            int total = NODEF / 4;
            k_accum<<<(total + 255) / 256, 256>>>(d_acc, e_dst);
        }
        float* tmp = e_src; e_src = e_dst; e_dst = tmp;
    }

    // Q side
    k_clock<<<BATCH, 64>>>(d_acc, cat_emb, uh3, users, thetas, d_Q);

    // item side
    {
        int total = M_PAD * 64;
        k_items<<<(total + 255) / 256, 256>>>(d_acc, cat_emb, item_cat, d_item);
    }

    // fused GEMM
    {
        dim3 grid(M_PAD / BN, BATCH / BM);
        k_gemm<<<grid, 256>>>(d_Q, d_item, out);
    }
}

// round 2
// speedup vs baseline: 1.6679x; 1.6679x over previous
#include <cuda_runtime.h>
#include <cuda_bf16.h>
#include <math_constants.h>

#define N_USERS   100000
#define M_ITEMS   50000
#define N_NODES   (N_USERS + M_ITEMS)
#define LATENT    64
#define N_CATS    1000
#define N_LAYERS  3
#define TIME_BINS 24
#define NNZ       4800000
#define BATCH     1024
#define ALPHA     0.5f
#define M_PAD     50048          // 391 * 128

#define NODEF (N_NODES * LATENT)   // 9.6M floats
#define SCAN_CHUNK 1024
#define NBLK ((N_NODES + SCAN_CHUNK - 1) / SCAN_CHUNK)   // 147

// ---------------- device scratch (static: no allocs allowed) ----------------
__device__ float g_e0[NODEF];
__device__ float g_e1[NODEF];
__device__ float g_acc[NODEF];
__device__ float g_Q[BATCH * 128];
__device__ float g_item[M_PAD * 128];
__device__ int2  g_edge[NNZ];          // (val bits, col) reordered by row
__device__ int   g_cnt[N_NODES];
__device__ int   g_rowstart[N_NODES];
__device__ int   g_cursor[N_NODES];
__device__ int   g_blocksums[NBLK];

// ---------------- init: e0 = acc = concat(user_emb, item_emb) ----------------
__global__ void k_init(const float* __restrict__ ue, const float* __restrict__ ie,
                       float* __restrict__ e0, float* __restrict__ acc) {
    int i = blockIdx.x * blockDim.x + threadIdx.x;       // float4 index
    const int total = N_NODES * (LATENT / 4);
    const int usplit = N_USERS * (LATENT / 4);
    if (i < total) {
        float4 v = (i < usplit) ? ((const float4*)ue)[i]
                                : ((const float4*)ie)[i - usplit];
        ((float4*)e0)[i] = v;
        ((float4*)acc)[i] = v;
    }
}

// ---------------- CSR build: count ----------------
__global__ void k_count(const int* __restrict__ rows, int* __restrict__ cnt) {
    int e = blockIdx.x * blockDim.x + threadIdx.x;
    if (e < NNZ) atomicAdd(&cnt[rows[e]], 1);
}

// ---------------- CSR build: per-chunk exclusive scan ----------------
__global__ __launch_bounds__(256) void k_scan_blocks(const int* __restrict__ cnt,
                                                     int* __restrict__ rowstart,
                                                     int* __restrict__ blocksums) {
    __shared__ int wsum[8];
    __shared__ int woff[8];
    int tid  = threadIdx.x;
    int lane = tid & 31;
    int warp = tid >> 5;
    int base = blockIdx.x * SCAN_CHUNK + tid * 4;

    int c0 = 0, c1 = 0, c2 = 0, c3 = 0;
    if (base + 3 < N_NODES) {
        int4 c = *(const int4*)(cnt + base);
        c0 = c.x; c1 = c.y; c2 = c.z; c3 = c.w;
    } else {
        if (base + 0 < N_NODES) c0 = cnt[base + 0];
        if (base + 1 < N_NODES) c1 = cnt[base + 1];
        if (base + 2 < N_NODES) c2 = cnt[base + 2];
        if (base + 3 < N_NODES) c3 = cnt[base + 3];
    }
    int tsum = c0 + c1 + c2 + c3;

    // warp inclusive scan of tsum
    int inc = tsum;
    #pragma unroll
    for (int off = 1; off < 32; off <<= 1) {
        int n = __shfl_up_sync(0xffffffffu, inc, off);
        if (lane >= off) inc += n;
    }
    if (lane == 31) wsum[warp] = inc;
    __syncthreads();
    if (tid == 0) {
        int r = 0;
        #pragma unroll
        for (int i = 0; i < 8; i++) { woff[i] = r; r += wsum[i]; }
        blocksums[blockIdx.x] = r;
    }
    __syncthreads();

    int excl = woff[warp] + (inc - tsum);   // exclusive prefix of this thread
    if (base + 0 < N_NODES) rowstart[base + 0] = excl;
    if (base + 1 < N_NODES) rowstart[base + 1] = excl + c0;
    if (base + 2 < N_NODES) rowstart[base + 2] = excl + c0 + c1;
    if (base + 3 < N_NODES) rowstart[base + 3] = excl + c0 + c1 + c2;
}

// ---------------- CSR build: scan chunk sums (serial, tiny) ----------------
__global__ void k_scan_sums(int* __restrict__ blocksums) {
    if (threadIdx.x == 0 && blockIdx.x == 0) {
        int r = 0;
        for (int i = 0; i < NBLK; i++) { int v = blocksums[i]; blocksums[i] = r; r += v; }
    }
}

// ---------------- CSR build: add chunk offsets; init cursor ----------------
__global__ void k_add_offsets(int* __restrict__ rowstart,
                              const int* __restrict__ blocksums,
                              int* __restrict__ cursor) {
    int i = blockIdx.x * blockDim.x + threadIdx.x;
    if (i < N_NODES) {
        int r = rowstart[i] + blocksums[i / SCAN_CHUNK];
        rowstart[i] = r;
        cursor[i]   = r;
    }
}

// ---------------- CSR build: fill edge list ----------------
__global__ void k_fill(const float* __restrict__ vals,
                       const int*   __restrict__ rows,
                       const int*   __restrict__ cols,
                       int* __restrict__ cursor,
                       int2* __restrict__ edge) {
    int e = blockIdx.x * blockDim.x + threadIdx.x;
    if (e < NNZ) {
        int r = rows[e];
        int pos = atomicAdd(&cursor[r], 1);
        edge[pos] = make_int2(__float_as_int(vals[e]), cols[e]);
    }
}

// ---------------- layer: atomic-free segment gather, fused acc += e ----------------
__global__ __launch_bounds__(256) void k_gather(const int2* __restrict__ edge,
                                                const int*  __restrict__ rowstart,
                                                const int*  __restrict__ cnt,
                                                const float* __restrict__ esrc,
                                                float*       __restrict__ edst,
                                                float*       __restrict__ acc,
                                                int writeE) {
    int g   = blockIdx.x * blockDim.x + threadIdx.x;
    int row = g >> 4;
    int t   = g & 15;
    if (row >= N_NODES) return;
    unsigned hmask = 0xFFFFu << (threadIdx.x & 16);   // own half-warp

    int start = rowstart[row];
    int deg   = cnt[row];
    float4 s = make_float4(0.f, 0.f, 0.f, 0.f);

    for (int base = 0; base < deg; base += 16) {
        int rem = deg - base;
        int2 ev = (t < rem) ? __ldg(&edge[start + base + t]) : make_int2(0, 0);
        int lim = rem < 16 ? rem : 16;
        #pragma unroll 4
        for (int k = 0; k < lim; k++) {
            float v = __int_as_float(__shfl_sync(hmask, ev.x, k, 16));
            int   c = __shfl_sync(hmask, ev.y, k, 16);
            float4 m = __ldg(&((const float4*)esrc)[c * (LATENT / 4) + t]);
            s.x += v * m.x; s.y += v * m.y; s.z += v * m.z; s.w += v * m.w;
        }
    }

    int idx = row * (LATENT / 4) + t;
    if (writeE) ((float4*)edst)[idx] = s;
    float4 a = ((float4*)acc)[idx];
    a.x += s.x; a.y += s.y; a.z += s.z; a.w += s.w;
    ((float4*)acc)[idx] = a;
}

// ---------------- clock: build Q[b] = [0.25*acc[user] | alpha * v_clock] ----------------
__global__ void k_clock(const float* __restrict__ acc,
                        const float* __restrict__ cat_emb,
                        const int*   __restrict__ uh3,
                        const int*   __restrict__ users,
                        const float* __restrict__ thetas,
                        float*       __restrict__ Q) {
    int b = blockIdx.x;
    int d = threadIdx.x;       // 64 threads
    __shared__ float w[TIME_BINS];
    __shared__ float sinv;
    int u = users[b];
    if (d < TIME_BINS) {
        float cur = thetas[b] * (float)(TIME_BINS / (2.0 * CUDART_PI));
        float diff = fabsf(cur - (float)d);
        float delta = fminf(diff, (float)TIME_BINS - diff);
        w[d] = __expf(-0.5f * delta * delta);
    }
    __syncthreads();
    if (d == 0) {
        float s = 0.f;
        #pragma unroll
        for (int h = 0; h < TIME_BINS; h++) s += w[h];
        sinv = 1.0f / (s + 1e-8f);
    }
    __syncthreads();
    float inv3 = sinv * (1.0f / 3.0f);
    float v = 0.f;
    const int* base = &uh3[u * TIME_BINS * 3];
    #pragma unroll 4
    for (int h = 0; h < TIME_BINS; h++) {
        int c0 = base[h * 3 + 0], c1 = base[h * 3 + 1], c2 = base[h * 3 + 2];
        float e = cat_emb[c0 * 64 + d] + cat_emb[c1 * 64 + d] + cat_emb[c2 * 64 + d];
        v += w[h] * e;
    }
    v *= inv3;
    Q[b * 128 + d]      = 0.25f * acc[u * LATENT + d];
    Q[b * 128 + 64 + d] = ALPHA * v;
}

// ---------------- items: IT[m] = [0.25*acc[N_USERS+m] | cat_emb[item_cat[m]]] ----------------
__global__ void k_items(const float* __restrict__ acc,
                        const float* __restrict__ cat_emb,
                        const int*   __restrict__ item_cat,
                        float*       __restrict__ IT) {
    int g = blockIdx.x * blockDim.x + threadIdx.x;
    int m = g >> 6;
    int d = g & 63;
    if (m < M_PAD) {
        if (m < M_ITEMS) {
            IT[m * 128 + d]      = 0.25f * acc[(N_USERS + m) * LATENT + d];
            IT[m * 128 + 64 + d] = cat_emb[item_cat[m] * 64 + d];
        } else {
            IT[m * 128 + d] = 0.f;
            IT[m * 128 + 64 + d] = 0.f;
        }
    }
}

// ---------------- GEMM: C[1024,50000] = Q[1024,128] @ IT[M_PAD,128]^T ----------------
#define BM 128
#define BN 128
#define BK 8
#define TM 8
#define TN 8

__global__ __launch_bounds__(256) void k_gemm(const float* __restrict__ A,
                                              const float* __restrict__ B,
                                              float* __restrict__ C) {
    __shared__ float As[BK][BM];
    __shared__ float Bs[BK][BN];
    const int tid  = threadIdx.x;
    const int row0 = blockIdx.y * BM;   // batch offset
    const int col0 = blockIdx.x * BN;   // item offset
    const int ty   = tid / 16;
    const int tx   = tid % 16;

    float acc[TM][TN];
    #pragma unroll
    for (int i = 0; i < TM; i++)
        #pragma unroll
        for (int j = 0; j < TN; j++) acc[i][j] = 0.f;

    const int lr = tid >> 1;          // 0..127
    const int lk = (tid & 1) * 4;     // 0 or 4

    #pragma unroll 1
    for (int k0 = 0; k0 < 128; k0 += BK) {
        float4 av = *(const float4*)(A + (row0 + lr) * 128 + k0 + lk);
        float4 bv = *(const float4*)(B + (col0 + lr) * 128 + k0 + lk);
        As[lk + 0][lr] = av.x; As[lk + 1][lr] = av.y;
        As[lk + 2][lr] = av.z; As[lk + 3][lr] = av.w;
        Bs[lk + 0][lr] = bv.x; Bs[lk + 1][lr] = bv.y;
        Bs[lk + 2][lr] = bv.z; Bs[lk + 3][lr] = bv.w;
        __syncthreads();
        #pragma unroll
        for (int kk = 0; kk < BK; kk++) {
            float a[TM], b[TN];
            #pragma unroll
            for (int i = 0; i < TM; i++) a[i] = As[kk][ty * TM + i];
            #pragma unroll
            for (int j = 0; j < TN; j++) b[j] = Bs[kk][tx * TN + j];
            #pragma unroll
            for (int i = 0; i < TM; i++)
                #pragma unroll
                for (int j = 0; j < TN; j++)
                    acc[i][j] += a[i] * b[j];
        }
        __syncthreads();
    }

    #pragma unroll
    for (int i = 0; i < TM; i++) {
        int r = row0 + ty * TM + i;            // always < 1024
        #pragma unroll
        for (int j = 0; j < TN; j += 4) {
            int c = col0 + tx * TN + j;
            if (c < M_ITEMS) {
                float4 v = make_float4(acc[i][j], acc[i][j + 1], acc[i][j + 2], acc[i][j + 3]);
                *(float4*)(C + r * M_ITEMS + c) = v;
            }
        }
    }
}

// ---------------- launch ----------------
extern "C" void kernel_launch(void* const* d_in, const int* in_sizes, int n_in,
                              void* d_out, int out_size) {
    const float* user_emb  = (const float*)d_in[0];
    const float* item_emb  = (const float*)d_in[1];
    const float* cat_emb   = (const float*)d_in[2];
    const float* graph_vals= (const float*)d_in[3];
    const int*   graph_rows= (const int*)  d_in[4];
    const int*   graph_cols= (const int*)  d_in[5];
    const int*   uh3       = (const int*)  d_in[6];
    const int*   item_cat  = (const int*)  d_in[7];
    const int*   users     = (const int*)  d_in[8];
    const float* thetas    = (const float*)d_in[9];
    float* out = (float*)d_out;

    float *d_e0, *d_e1, *d_acc, *d_Q, *d_item;
    int2* d_edge; int *d_cnt, *d_rowstart, *d_cursor, *d_blocksums;
    cudaGetSymbolAddress((void**)&d_e0,       g_e0);
    cudaGetSymbolAddress((void**)&d_e1,       g_e1);
    cudaGetSymbolAddress((void**)&d_acc,      g_acc);
    cudaGetSymbolAddress((void**)&d_Q,        g_Q);
    cudaGetSymbolAddress((void**)&d_item,     g_item);
    cudaGetSymbolAddress((void**)&d_edge,     g_edge);
    cudaGetSymbolAddress((void**)&d_cnt,      g_cnt);
    cudaGetSymbolAddress((void**)&d_rowstart, g_rowstart);
    cudaGetSymbolAddress((void**)&d_cursor,   g_cursor);
    cudaGetSymbolAddress((void**)&d_blocksums,g_blocksums);

    // ---- CSR build (once; reused by all 3 layers) ----
    cudaMemsetAsync(d_cnt, 0, (size_t)N_NODES * sizeof(int), 0);
    k_count<<<(NNZ + 255) / 256, 256>>>(graph_rows, d_cnt);
    k_scan_blocks<<<NBLK, 256>>>(d_cnt, d_rowstart, d_blocksums);
    k_scan_sums<<<1, 32>>>(d_blocksums);
    k_add_offsets<<<(N_NODES + 255) / 256, 256>>>(d_rowstart, d_blocksums, d_cursor);
    k_fill<<<(NNZ + 255) / 256, 256>>>(graph_vals, graph_rows, graph_cols, d_cursor, d_edge);

    // ---- init embeddings ----
    {
        int total = N_NODES * (LATENT / 4);
        k_init<<<(total + 255) / 256, 256>>>(user_emb, item_emb, d_e0, d_acc);
    }

    // ---- 3 LightGCN layers: atomic-free gather, fused accumulate ----
    {
        int th = N_NODES * 16;
        int blocks = (th + 255) / 256;
        k_gather<<<blocks, 256>>>(d_edge, d_rowstart, d_cnt, d_e0, d_e1, d_acc, 1);
        k_gather<<<blocks, 256>>>(d_edge, d_rowstart, d_cnt, d_e1, d_e0, d_acc, 1);
        k_gather<<<blocks, 256>>>(d_edge, d_rowstart, d_cnt, d_e0, d_e1, d_acc, 0);
    }

    // ---- Q side ----
    k_clock<<<BATCH, 64>>>(d_acc, cat_emb, uh3, users, thetas, d_Q);

    // ---- item side ----
    {
        int total = M_PAD * 64;
        k_items<<<(total + 255) / 256, 256>>>(d_acc, cat_emb, item_cat, d_item);
    }

    // ---- fused GEMM ----
    {
        dim3 grid(M_PAD / BN, BATCH / BM);
        k_gemm<<<grid, 256>>>(d_Q, d_item, out);
    }
}